// round 15
// baseline (speedup 1.0000x reference)
#include <cuda_runtime.h>
#include <cuda_fp16.h>
#include <cuda_bf16.h>

typedef unsigned int u32;
typedef unsigned long long u64;

#define EPS_BN 1e-5f

// ---------------- static device scratch ----------------
__device__ __align__(16) float g_H[65536*100];     // relu(gemm) [row][100]
__device__ __align__(16) float g_O1[50*65536];     // head L1 out, [j][slot]
__device__ __align__(16) u32   g_Bf[64*1664];      // B fp16 fragments
__device__ float g_bc[104];
__device__ __align__(16) float g_W1f[8*100*50];
__device__ float g_b1f[8*50];
__device__ __align__(16) float g_W2f[8*50*128];
__device__ float g_b2f[8*128];
__device__ int g_blkcnt[256*8];
__device__ unsigned char g_hidx[65536];
__device__ int g_order[65536];

// ---------------- helpers ----------------
__device__ __forceinline__ u32 smem_u32(const void* p){
    u32 a; asm("{ .reg .u64 t; cvta.to.shared.u64 t, %1; cvt.u32.u64 %0, t; }" : "=r"(a) : "l"(p)); return a;
}
__device__ __forceinline__ void cp_async16(u32 dst, const void* src){
    u64 g = (u64)__cvta_generic_to_global(src);
    asm volatile("cp.async.cg.shared.global [%0], [%1], 16;" :: "r"(dst), "l"(g) : "memory");
}
__device__ __forceinline__ void cp_commit(){ asm volatile("cp.async.commit_group;" ::: "memory"); }
__device__ __forceinline__ void cp_wait0(){ asm volatile("cp.async.wait_group 0;" ::: "memory"); }
__device__ __forceinline__ void ldm4(u32* d, u32 addr){
    asm volatile("ldmatrix.sync.aligned.m8n8.x4.shared.b16 {%0,%1,%2,%3}, [%4];"
        : "=r"(d[0]), "=r"(d[1]), "=r"(d[2]), "=r"(d[3]) : "r"(addr));
}
__device__ __forceinline__ void mma_f16(float* c, const u32* a, u32 b0, u32 b1){
    asm volatile("mma.sync.aligned.m16n8k16.row.col.f32.f16.f16.f32 "
        "{%0,%1,%2,%3}, {%4,%5,%6,%7}, {%8,%9}, {%0,%1,%2,%3};"
        : "+f"(c[0]), "+f"(c[1]), "+f"(c[2]), "+f"(c[3])
        : "r"(a[0]), "r"(a[1]), "r"(a[2]), "r"(a[3]), "r"(b0), "r"(b1));
}
__device__ __forceinline__ u32 packh2(float x, float y){
    __half2 h = __floats2half2_rn(x, y);
    return *(u32*)&h;
}
// packed fp32x2 helpers
__device__ __forceinline__ u64 pack2(float x, float y){
    u64 r; asm("mov.b64 %0, {%1, %2};" : "=l"(r) : "f"(x), "f"(y)); return r;
}
__device__ __forceinline__ float2 unpack2(u64 a){
    float2 r; asm("mov.b64 {%0, %1}, %2;" : "=f"(r.x), "=f"(r.y) : "l"(a)); return r;
}
__device__ __forceinline__ void fma2(u64& acc, u64 ab, u64 w){
    asm("fma.rn.f32x2 %0, %1, %2, %0;" : "+l"(acc) : "l"(ab), "l"(w));
}

// ---------------- 1: fused prep (B frags + BN folds + classify) ----------------
__global__ void k_prep(const float* __restrict__ x,
                       const float* __restrict__ Wn, const float* __restrict__ v0,
                       const float* __restrict__ m0, const float* __restrict__ bn,
                       const float* __restrict__ m1, const float* __restrict__ v1,
                       const float* __restrict__ W1, const float* __restrict__ b1,
                       const float* __restrict__ m2, const float* __restrict__ v2,
                       const float* __restrict__ W2, const float* __restrict__ b2){
    int blk = blockIdx.x, tid = threadIdx.x;
    if (blk < 416){
        int i = blk*256 + tid;                 // 106496 B fragments
        int c = i / 1664;
        int rr = i % 1664;
        int reg = rr & 1;
        int t = rr >> 1;
        int lane = t & 31;
        int t2 = t >> 5;
        int nt = t2 % 13;
        int ks = t2 / 13;
        int k0 = c*32 + ks*16 + reg*8 + 2*(lane & 3);
        int n  = nt*8 + (lane >> 2);
        float a = 0.f, b = 0.f;
        if (n < 100){
            a = Wn[k0*100 + n]     * rsqrtf(__ldg(v0 + k0)   + EPS_BN);
            b = Wn[(k0+1)*100 + n] * rsqrtf(__ldg(v0 + k0+1) + EPS_BN);
        }
        g_Bf[i] = packh2(a, b);
        return;
    }
    if (blk < 672){                            // classify: 256 blocks
        __shared__ int c8[8];
        int cb = blk - 416;
        if (tid < 8) c8[tid] = 0;
        __syncthreads();
        int r = cb*256 + tid;
        const float* xr = x + (size_t)r*2051;
        int idx = ((__ldg(xr)>0.5f)?4:0) | ((__ldg(xr+1)>0.5f)?2:0) | ((__ldg(xr+2)>0.5f)?1:0);
        g_hidx[r] = (unsigned char)idx;
        atomicAdd(&c8[idx], 1);
        __syncthreads();
        if (tid < 8) g_blkcnt[cb*8 + tid] = c8[tid];
        return;
    }
    int sblk = blk - 672;
    if (sblk < 100){
        __shared__ float red[256];
        int n = sblk;
        float s = 0.f;
        for (int k = tid; k < 2048; k += 256)
            s += m0[k] * rsqrtf(v0[k] + EPS_BN) * Wn[k*100 + n];
        red[tid] = s; __syncthreads();
        for (int st = 128; st; st >>= 1){ if (tid < st) red[tid] += red[tid + st]; __syncthreads(); }
        if (tid == 0) g_bc[n] = bn[n] - red[0];
    } else if (sblk < 257){
        int i = (sblk - 100)*256 + tid;
        if (i < 40000){ int d = (i / 50) % 100; g_W1f[i] = W1[i] * rsqrtf(v1[d] + EPS_BN); }
    } else if (sblk < 259){
        int i = (sblk - 257)*256 + tid;
        if (i < 400){
            int h = i / 50, j = i % 50;
            float s = 0.f;
            for (int d = 0; d < 100; d++)
                s += m1[d] * rsqrtf(v1[d] + EPS_BN) * W1[(h*100 + d)*50 + j];
            g_b1f[i] = b1[i] - s;
        }
    } else if (sblk < 459){
        int i = (sblk - 259)*256 + tid;
        if (i < 51200){ int hj = i >> 7; g_W2f[i] = W2[i] * rsqrtf(v2[hj] + EPS_BN); }
    } else {
        int i = (sblk - 459)*256 + tid;
        if (i < 1024){
            int h = i >> 7, d = i & 127;
            float s = 0.f;
            for (int j = 0; j < 50; j++){
                int hj = h*50 + j;
                s += m2[hj] * rsqrtf(v2[hj] + EPS_BN) * W2[hj*128 + d];
            }
            g_b2f[i] = b2[i] - s;
        }
    }
}

// ---------------- 2: scatter with built-in scan ----------------
__global__ void k_scatter(){
    __shared__ int ssum[256];
    __shared__ int base8[8];
    __shared__ int c8[8];
    int t = threadIdx.x, blk = blockIdx.x;
    int v[8]; int s = 0;
    #pragma unroll
    for (int u = 0; u < 8; u++){
        int idx = t*8 + u;                     // idx = h*256 + b (head-major)
        v[u] = g_blkcnt[(idx & 255)*8 + (idx >> 8)];
        s += v[u];
    }
    ssum[t] = s; __syncthreads();
    for (int st = 1; st < 256; st <<= 1){
        int a = (t >= st) ? ssum[t - st] : 0;
        __syncthreads();
        ssum[t] += a;
        __syncthreads();
    }
    int base = t ? ssum[t-1] : 0;
    if (t < 8) c8[t] = 0;
    #pragma unroll
    for (int u = 0; u < 8; u++){
        int idx = t*8 + u;
        if ((idx & 255) == blk) base8[idx >> 8] = base;
        base += v[u];
    }
    __syncthreads();
    int r = blk*256 + t;
    int idx = g_hidx[r];
    int rank = atomicAdd(&c8[idx], 1);
    g_order[base8[idx] + rank] = r;
}

// ---------------- 3: main GEMM: EXACT R7 shape (locked: ~152us) ----------------
// smem: A0[10240] A1[10240] B0[6656] B1[6656] = 33792 B
static constexpr int ABUF = 10240;
static constexpr int BOFF = 20480;
static constexpr int BBUF = 6656;

template<int NT, int NTBASE>
__device__ __forceinline__ void compute_chunk(u32 abase, const uint2* __restrict__ Bs,
                                              float (&acc)[2][7][4], int warpM, int lane){
    int rbase = warpM + (lane & 7) + ((lane >> 3) & 1)*8;
    int kcol  = (lane >> 4)*8;
    #pragma unroll
    for (int ks = 0; ks < 2; ks++){
        uint2 b[NT];
        #pragma unroll
        for (int nt = 0; nt < NT; nt++)
            b[nt] = Bs[(ks*13 + NTBASE + nt)*32 + lane];
        u32 ah[2][4];
        #pragma unroll
        for (int mt = 0; mt < 2; mt++){
            u32 ad = abase + (u32)(((rbase + mt*16)*40 + ks*16 + kcol)*2);
            ldm4(ah[mt], ad);
        }
        #pragma unroll
        for (int nt = 0; nt < NT; nt++)
            #pragma unroll
            for (int mt = 0; mt < 2; mt++)
                mma_f16(acc[mt][nt], ah[mt], b[nt].x, b[nt].y);
    }
}

__global__ void __launch_bounds__(256, 2) k_gemm(const float* __restrict__ x){
    extern __shared__ char sm[];
    __shared__ float sbc[104];
    int tid = threadIdx.x, lane = tid & 31, wid = tid >> 5;
    int warpM = (wid & 3) * 32;
    int wcol = wid >> 2;                       // 0: nt 0-6, 1: nt 7-12
    if (tid < 104) sbc[tid] = (tid < 100) ? g_bc[tid] : 0.f;
    u32 sa = smem_u32(sm);

    const size_t row0 = (size_t)blockIdx.x * 128;
    float acc[2][7][4];
    #pragma unroll
    for (int a = 0; a < 2; a++)
        #pragma unroll
        for (int b = 0; b < 7; b++)
            #pragma unroll
            for (int c = 0; c < 4; c++) acc[a][b][c] = 0.f;

    float2 pre[8];
    auto lda = [&](int c){
        #pragma unroll
        for (int j = 0; j < 8; j++){
            int e = tid + j*256;
            int r = e >> 4, kp = e & 15;
            const float* p = x + (row0 + r)*2051 + 3 + c*32 + kp*2;
            pre[j].x = __ldg(p); pre[j].y = __ldg(p + 1);
        }
    };
    auto sts = [&](char* buf){
        #pragma unroll
        for (int j = 0; j < 8; j++){
            int e = tid + j*256;
            int r = e >> 4, kp = e & 15;
            int off = (r*40 + kp*2)*2;
            *(u32*)(buf + off) = packh2(pre[j].x, pre[j].y);
        }
    };
    auto cpB = [&](int c, int buf){
        u32 dst = sa + BOFF + (u32)(buf*BBUF);
        const char* src = (const char*)g_Bf + (size_t)c*BBUF;
        #pragma unroll
        for (int i = 0; i < 2; i++){
            int e = tid + i*256;
            if (e < 416) cp_async16(dst + e*16, src + e*16);
        }
    };

    cpB(0, 0); cp_commit();
    lda(0); sts(sm);
    cp_wait0();
    __syncthreads();

    for (int c = 0; c < 64; c++){
        if (c < 63){ cpB(c + 1, (c + 1) & 1); cp_commit(); lda(c + 1); }
        u32 abase = sa + (u32)((c & 1)*ABUF);
        const uint2* Bs = (const uint2*)(sm + BOFF + (c & 1)*BBUF);
        if (wcol == 0) compute_chunk<7,0>(abase, Bs, acc, warpM, lane);
        else           compute_chunk<6,7>(abase, Bs, acc, warpM, lane);
        if (c < 63) sts(sm + ((c + 1) & 1)*ABUF);
        cp_wait0();
        __syncthreads();
    }

    int NT = wcol ? 6 : 7, ntbase = wcol ? 7 : 0;
    #pragma unroll
    for (int mt = 0; mt < 2; mt++){
        for (int nt = 0; nt < NT; nt++){
            int col = (ntbase + nt)*8 + 2*(lane & 3);
            if (col < 100){
                int r = (int)row0 + warpM + mt*16 + (lane >> 2);
                float b0 = sbc[col], b1 = sbc[col + 1];
                g_H[r*100 + col]           = fmaxf(acc[mt][nt][0] + b0, 0.f);
                g_H[r*100 + col + 1]       = fmaxf(acc[mt][nt][1] + b1, 0.f);
                g_H[(r + 8)*100 + col]     = fmaxf(acc[mt][nt][2] + b0, 0.f);
                g_H[(r + 8)*100 + col + 1] = fmaxf(acc[mt][nt][3] + b1, 0.f);
            }
        }
    }
}

// ---------------- 4: head layer 1 — 2 samples x half-outputs per thread ----------------
// 512 blocks x 128 threads; block covers 128 slots.
// thread t: pair p = t&63 -> samples (slot0+2p, slot0+2p+1); half = t>>6 -> outputs [half*26, half*26+26)
__global__ void __launch_bounds__(128) k_head1(){
    __shared__ __align__(16) float sW1[100*52];
    __shared__ __align__(8) float sb1[52];
    int tid = threadIdx.x;
    int p = tid & 63, half = tid >> 6;
    int slot0 = blockIdx.x*128;                // FIX: was blk*256 in R14 (half the samples skipped)
    int s0 = slot0 + 2*p, s1 = s0 + 1;
    int r0 = g_order[s0], r1 = g_order[s1];
    int h0 = g_hidx[r0], h1 = g_hidx[r1];
    for (int hd = 0; hd < 8; hd++){
        bool any = (h0 == hd) || (h1 == hd);
        if (!__syncthreads_or(any)) continue;
        for (int i = tid; i < 5200; i += 128){
            int d = i / 52, j = i % 52;
            sW1[i] = (j < 50) ? g_W1f[hd*5000 + d*50 + j] : 0.f;
        }
        if (tid < 52) sb1[tid] = (tid < 50) ? g_b1f[hd*50 + tid] : 0.f;
        __syncthreads();
        if (any){
            u64 a0[13], a1[13];
            #pragma unroll
            for (int k = 0; k < 13; k++){
                u64 b = *(const u64*)&sb1[half*26 + 2*k];
                a0[k] = b; a1[k] = b;
            }
            const float4* hp0 = (const float4*)(g_H + (size_t)r0*100);
            const float4* hp1 = (const float4*)(g_H + (size_t)r1*100);
            for (int dv = 0; dv < 25; dv++){
                float4 v0 = hp0[dv], v1 = hp1[dv];
                float f0[4] = {v0.x, v0.y, v0.z, v0.w};
                float f1[4] = {v1.x, v1.y, v1.z, v1.w};
                #pragma unroll
                for (int s = 0; s < 4; s++){
                    int d = dv*4 + s;
                    const u64* w = (const u64*)(sW1 + d*52 + half*26);
                    u64 vv0 = pack2(f0[s], f0[s]);
                    u64 vv1 = pack2(f1[s], f1[s]);
                    #pragma unroll
                    for (int k = 0; k < 13; k++){
                        u64 wv = w[k];                 // LDS.64 broadcast, reused for both samples
                        fma2(a0[k], vv0, wv);
                        fma2(a1[k], vv1, wv);
                    }
                }
            }
            int jb = half*26;
            if (h0 == hd){
                #pragma unroll
                for (int k = 0; k < 13; k++){
                    float2 o = unpack2(a0[k]);
                    int j = jb + 2*k;
                    if (j < 50)     g_O1[j*65536 + s0]       = fmaxf(o.x, 0.f);
                    if (j + 1 < 50) g_O1[(j + 1)*65536 + s0] = fmaxf(o.y, 0.f);
                }
            }
            if (h1 == hd){
                #pragma unroll
                for (int k = 0; k < 13; k++){
                    float2 o = unpack2(a1[k]);
                    int j = jb + 2*k;
                    if (j < 50)     g_O1[j*65536 + s1]       = fmaxf(o.x, 0.f);
                    if (j + 1 < 50) g_O1[(j + 1)*65536 + s1] = fmaxf(o.y, 0.f);
                }
            }
        }
        __syncthreads();
    }
}

// ---------------- 5: head layer 2 (packed f32x2) ----------------
// dyn smem: so1[128*52] @0, sW2[8 x 812] @26624, sb2[128] @52608
__global__ void __launch_bounds__(256) k_head2(float* __restrict__ out){
    extern __shared__ char hsm[];
    float* so1 = (float*)hsm;
    float* sW2 = (float*)(hsm + 26624);
    float* sb2 = (float*)(hsm + 52608);
    int tid = threadIdx.x;
    int slot0 = blockIdx.x*128;
    for (int i = tid; i < 6400; i += 256){
        int j = i >> 7, s = i & 127;
        so1[s*52 + j] = g_O1[j*65536 + slot0 + s];
    }
    int q = tid & 7;
    int sg = tid >> 3;
    int rows[4]; int hh[4];
    #pragma unroll
    for (int s = 0; s < 4; s++){
        rows[s] = g_order[slot0 + sg*4 + s];
        hh[s] = g_hidx[rows[s]];
    }
    for (int hd = 0; hd < 8; hd++){
        bool any = (hh[0]==hd)||(hh[1]==hd)||(hh[2]==hd)||(hh[3]==hd);
        if (!__syncthreads_or(any)) continue;
        for (int i = tid; i < 6400; i += 256){
            int j = i >> 7, d = i & 127, qq = d >> 4, cc = d & 15;
            sW2[qq*812 + j*16 + cc] = g_W2f[hd*6400 + i];
        }
        if (tid < 128) sb2[tid] = g_b2f[hd*128 + tid];
        __syncthreads();
        if (any){
            u64 accp[4][8];
            #pragma unroll
            for (int s = 0; s < 4; s++)
                #pragma unroll
                for (int u = 0; u < 8; u++)
                    accp[s][u] = *(const u64*)&sb2[q*16 + 2*u];
            const ulonglong2* wq = (const ulonglong2*)(sW2 + q*812);
            for (int j = 0; j < 50; j++){
                ulonglong2 w[4];
                #pragma unroll
                for (int u = 0; u < 4; u++) w[u] = wq[j*4 + u];
                #pragma unroll
                for (int s = 0; s < 4; s++){
                    float v = so1[(sg*4 + s)*52 + j];
                    u64 vv = pack2(v, v);
                    #pragma unroll
                    for (int u = 0; u < 4; u++){
                        fma2(accp[s][2*u],     vv, w[u].x);
                        fma2(accp[s][2*u + 1], vv, w[u].y);
                    }
                }
            }
            #pragma unroll
            for (int s = 0; s < 4; s++){
                if (hh[s] == hd){
                    float4* op = (float4*)(out + (size_t)rows[s]*128 + q*16);
                    #pragma unroll
                    for (int u = 0; u < 4; u++){
                        float2 a = unpack2(accp[s][2*u]);
                        float2 b = unpack2(accp[s][2*u + 1]);
                        op[u] = make_float4(a.x, a.y, b.x, b.y);
                    }
                }
            }
        }
        __syncthreads();
    }
}

// ---------------- launch (k_head1 at slot #4 for ncu) ----------------
extern "C" void kernel_launch(void* const* d_in, const int* in_sizes, int n_in,
                              void* d_out, int out_size){
    (void)in_sizes; (void)n_in; (void)out_size;
    const float* x  = (const float*)d_in[0];
    const float* m0 = (const float*)d_in[1];
    const float* v0 = (const float*)d_in[2];
    const float* Wn = (const float*)d_in[3];
    const float* bn = (const float*)d_in[4];
    const float* m1 = (const float*)d_in[5];
    const float* v1 = (const float*)d_in[6];
    const float* W1 = (const float*)d_in[7];
    const float* b1 = (const float*)d_in[8];
    const float* m2 = (const float*)d_in[9];
    const float* v2 = (const float*)d_in[10];
    const float* W2 = (const float*)d_in[11];
    const float* b2 = (const float*)d_in[12];
    float* out = (float*)d_out;

    cudaFuncSetAttribute(k_gemm,  cudaFuncAttributeMaxDynamicSharedMemorySize, 33792);
    cudaFuncSetAttribute(k_head2, cudaFuncAttributeMaxDynamicSharedMemorySize, 53120);

    k_prep<<<1135, 256>>>(x, Wn, v0, m0, bn, m1, v1, W1, b1, m2, v2, W2, b2); // 1 (incl. classify)
    k_scatter<<<256, 256>>>();                             // 2
    k_gemm<<<512, 256, 33792>>>(x);                        // 3
    k_head1<<<512, 128>>>();                               // 4  <- ncu profiles launch #4
    k_head2<<<512, 256, 53120>>>(out);                     // 5
}

// round 16
// speedup vs baseline: 1.3374x; 1.3374x over previous
#include <cuda_runtime.h>
#include <cuda_fp16.h>
#include <cuda_bf16.h>

typedef unsigned int u32;
typedef unsigned long long u64;

#define EPS_BN 1e-5f

// ---------------- static device scratch ----------------
__device__ __align__(16) float g_H[65536*100];     // relu(gemm) [row][100]
__device__ __align__(16) float g_O1[50*65536];     // head L1 out, [j][slot]
__device__ __align__(16) u32   g_Bf[64*1664];      // B fp16 fragments
__device__ float g_bc[104];
__device__ __align__(16) float g_W1f[8*100*50];
__device__ float g_b1f[8*50];
__device__ __align__(16) float g_W2f[8*50*128];
__device__ float g_b2f[8*128];
__device__ int g_blkcnt[256*8];
__device__ unsigned char g_hidx[65536];
__device__ int g_order[65536];

// ---------------- helpers ----------------
__device__ __forceinline__ u32 smem_u32(const void* p){
    u32 a; asm("{ .reg .u64 t; cvta.to.shared.u64 t, %1; cvt.u32.u64 %0, t; }" : "=r"(a) : "l"(p)); return a;
}
__device__ __forceinline__ void cp_async16(u32 dst, const void* src){
    u64 g = (u64)__cvta_generic_to_global(src);
    asm volatile("cp.async.cg.shared.global [%0], [%1], 16;" :: "r"(dst), "l"(g) : "memory");
}
__device__ __forceinline__ void cp_commit(){ asm volatile("cp.async.commit_group;" ::: "memory"); }
__device__ __forceinline__ void cp_wait0(){ asm volatile("cp.async.wait_group 0;" ::: "memory"); }
__device__ __forceinline__ void ldm4(u32* d, u32 addr){
    asm volatile("ldmatrix.sync.aligned.m8n8.x4.shared.b16 {%0,%1,%2,%3}, [%4];"
        : "=r"(d[0]), "=r"(d[1]), "=r"(d[2]), "=r"(d[3]) : "r"(addr));
}
__device__ __forceinline__ void mma_f16(float* c, const u32* a, u32 b0, u32 b1){
    asm volatile("mma.sync.aligned.m16n8k16.row.col.f32.f16.f16.f32 "
        "{%0,%1,%2,%3}, {%4,%5,%6,%7}, {%8,%9}, {%0,%1,%2,%3};"
        : "+f"(c[0]), "+f"(c[1]), "+f"(c[2]), "+f"(c[3])
        : "r"(a[0]), "r"(a[1]), "r"(a[2]), "r"(a[3]), "r"(b0), "r"(b1));
}
__device__ __forceinline__ u32 packh2(float x, float y){
    __half2 h = __floats2half2_rn(x, y);
    return *(u32*)&h;
}
// packed fp32x2 helpers
__device__ __forceinline__ u64 pack2(float x, float y){
    u64 r; asm("mov.b64 %0, {%1, %2};" : "=l"(r) : "f"(x), "f"(y)); return r;
}
__device__ __forceinline__ float2 unpack2(u64 a){
    float2 r; asm("mov.b64 {%0, %1}, %2;" : "=f"(r.x), "=f"(r.y) : "l"(a)); return r;
}
__device__ __forceinline__ void fma2(u64& acc, u64 ab, u64 w){
    asm("fma.rn.f32x2 %0, %1, %2, %0;" : "+l"(acc) : "l"(ab), "l"(w));
}

// ---------------- 1: fused prep (B frags + all BN folds) ----------------
__global__ void k_prep(const float* __restrict__ Wn, const float* __restrict__ v0,
                       const float* __restrict__ m0, const float* __restrict__ bn,
                       const float* __restrict__ m1, const float* __restrict__ v1,
                       const float* __restrict__ W1, const float* __restrict__ b1,
                       const float* __restrict__ m2, const float* __restrict__ v2,
                       const float* __restrict__ W2, const float* __restrict__ b2){
    int blk = blockIdx.x, tid = threadIdx.x;
    if (blk < 416){
        int i = blk*256 + tid;                 // 106496 B fragments
        int c = i / 1664;
        int rr = i % 1664;
        int reg = rr & 1;
        int t = rr >> 1;
        int lane = t & 31;
        int t2 = t >> 5;
        int nt = t2 % 13;
        int ks = t2 / 13;
        int k0 = c*32 + ks*16 + reg*8 + 2*(lane & 3);
        int n  = nt*8 + (lane >> 2);
        float a = 0.f, b = 0.f;
        if (n < 100){
            a = Wn[k0*100 + n]     * rsqrtf(__ldg(v0 + k0)   + EPS_BN);
            b = Wn[(k0+1)*100 + n] * rsqrtf(__ldg(v0 + k0+1) + EPS_BN);
        }
        g_Bf[i] = packh2(a, b);
        return;
    }
    int sblk = blk - 416;
    if (sblk < 100){
        __shared__ float red[256];
        int n = sblk;
        float s = 0.f;
        for (int k = tid; k < 2048; k += 256)
            s += m0[k] * rsqrtf(v0[k] + EPS_BN) * Wn[k*100 + n];
        red[tid] = s; __syncthreads();
        for (int st = 128; st; st >>= 1){ if (tid < st) red[tid] += red[tid + st]; __syncthreads(); }
        if (tid == 0) g_bc[n] = bn[n] - red[0];
    } else if (sblk < 257){
        int i = (sblk - 100)*256 + tid;
        if (i < 40000){ int d = (i / 50) % 100; g_W1f[i] = W1[i] * rsqrtf(v1[d] + EPS_BN); }
    } else if (sblk < 259){
        int i = (sblk - 257)*256 + tid;
        if (i < 400){
            int h = i / 50, j = i % 50;
            float s = 0.f;
            for (int d = 0; d < 100; d++)
                s += m1[d] * rsqrtf(v1[d] + EPS_BN) * W1[(h*100 + d)*50 + j];
            g_b1f[i] = b1[i] - s;
        }
    } else if (sblk < 459){
        int i = (sblk - 259)*256 + tid;
        if (i < 51200){ int hj = i >> 7; g_W2f[i] = W2[i] * rsqrtf(v2[hj] + EPS_BN); }
    } else {
        int i = (sblk - 459)*256 + tid;
        if (i < 1024){
            int h = i >> 7, d = i & 127;
            float s = 0.f;
            for (int j = 0; j < 50; j++){
                int hj = h*50 + j;
                s += m2[hj] * rsqrtf(v2[hj] + EPS_BN) * W2[hj*128 + d];
            }
            g_b2f[i] = b2[i] - s;
        }
    }
}

// ---------------- 2: classify (per-block histogram) ----------------
__global__ void k_classify(const float* __restrict__ x){
    __shared__ int c8[8];
    int tid = threadIdx.x;
    if (tid < 8) c8[tid] = 0;
    __syncthreads();
    int r = blockIdx.x*256 + tid;
    const float* xr = x + (size_t)r*2051;
    int idx = ((__ldg(xr)>0.5f)?4:0) | ((__ldg(xr+1)>0.5f)?2:0) | ((__ldg(xr+2)>0.5f)?1:0);
    g_hidx[r] = (unsigned char)idx;
    atomicAdd(&c8[idx], 1);
    __syncthreads();
    if (tid < 8) g_blkcnt[blockIdx.x*8 + tid] = c8[tid];
}

// ---------------- 3: scatter with built-in scan ----------------
__global__ void k_scatter(){
    __shared__ int ssum[256];
    __shared__ int base8[8];
    __shared__ int c8[8];
    int t = threadIdx.x, blk = blockIdx.x;
    int v[8]; int s = 0;
    #pragma unroll
    for (int u = 0; u < 8; u++){
        int idx = t*8 + u;                     // idx = h*256 + b (head-major)
        v[u] = g_blkcnt[(idx & 255)*8 + (idx >> 8)];
        s += v[u];
    }
    ssum[t] = s; __syncthreads();
    for (int st = 1; st < 256; st <<= 1){
        int a = (t >= st) ? ssum[t - st] : 0;
        __syncthreads();
        ssum[t] += a;
        __syncthreads();
    }
    int base = t ? ssum[t-1] : 0;
    if (t < 8) c8[t] = 0;
    #pragma unroll
    for (int u = 0; u < 8; u++){
        int idx = t*8 + u;
        if ((idx & 255) == blk) base8[idx >> 8] = base;
        base += v[u];
    }
    __syncthreads();
    int r = blk*256 + t;
    int idx = g_hidx[r];
    int rank = atomicAdd(&c8[idx], 1);
    g_order[base8[idx] + rank] = r;
}

// ---------------- 4: main GEMM: EXACT R7 shape (locked: ~152us) ----------------
// smem: A0[10240] A1[10240] B0[6656] B1[6656] = 33792 B
static constexpr int ABUF = 10240;
static constexpr int BOFF = 20480;
static constexpr int BBUF = 6656;

template<int NT, int NTBASE>
__device__ __forceinline__ void compute_chunk(u32 abase, const uint2* __restrict__ Bs,
                                              float (&acc)[2][7][4], int warpM, int lane){
    int rbase = warpM + (lane & 7) + ((lane >> 3) & 1)*8;
    int kcol  = (lane >> 4)*8;
    #pragma unroll
    for (int ks = 0; ks < 2; ks++){
        uint2 b[NT];
        #pragma unroll
        for (int nt = 0; nt < NT; nt++)
            b[nt] = Bs[(ks*13 + NTBASE + nt)*32 + lane];
        u32 ah[2][4];
        #pragma unroll
        for (int mt = 0; mt < 2; mt++){
            u32 ad = abase + (u32)(((rbase + mt*16)*40 + ks*16 + kcol)*2);
            ldm4(ah[mt], ad);
        }
        #pragma unroll
        for (int nt = 0; nt < NT; nt++)
            #pragma unroll
            for (int mt = 0; mt < 2; mt++)
                mma_f16(acc[mt][nt], ah[mt], b[nt].x, b[nt].y);
    }
}

__global__ void __launch_bounds__(256, 2) k_gemm(const float* __restrict__ x){
    extern __shared__ char sm[];
    __shared__ float sbc[104];
    int tid = threadIdx.x, lane = tid & 31, wid = tid >> 5;
    int warpM = (wid & 3) * 32;
    int wcol = wid >> 2;                       // 0: nt 0-6, 1: nt 7-12
    if (tid < 104) sbc[tid] = (tid < 100) ? g_bc[tid] : 0.f;
    u32 sa = smem_u32(sm);

    const size_t row0 = (size_t)blockIdx.x * 128;
    float acc[2][7][4];
    #pragma unroll
    for (int a = 0; a < 2; a++)
        #pragma unroll
        for (int b = 0; b < 7; b++)
            #pragma unroll
            for (int c = 0; c < 4; c++) acc[a][b][c] = 0.f;

    float2 pre[8];
    auto lda = [&](int c){
        #pragma unroll
        for (int j = 0; j < 8; j++){
            int e = tid + j*256;
            int r = e >> 4, kp = e & 15;
            const float* p = x + (row0 + r)*2051 + 3 + c*32 + kp*2;
            pre[j].x = __ldg(p); pre[j].y = __ldg(p + 1);
        }
    };
    auto sts = [&](char* buf){
        #pragma unroll
        for (int j = 0; j < 8; j++){
            int e = tid + j*256;
            int r = e >> 4, kp = e & 15;
            int off = (r*40 + kp*2)*2;
            *(u32*)(buf + off) = packh2(pre[j].x, pre[j].y);
        }
    };
    auto cpB = [&](int c, int buf){
        u32 dst = sa + BOFF + (u32)(buf*BBUF);
        const char* src = (const char*)g_Bf + (size_t)c*BBUF;
        #pragma unroll
        for (int i = 0; i < 2; i++){
            int e = tid + i*256;
            if (e < 416) cp_async16(dst + e*16, src + e*16);
        }
    };

    cpB(0, 0); cp_commit();
    lda(0); sts(sm);
    cp_wait0();
    __syncthreads();

    for (int c = 0; c < 64; c++){
        if (c < 63){ cpB(c + 1, (c + 1) & 1); cp_commit(); lda(c + 1); }
        u32 abase = sa + (u32)((c & 1)*ABUF);
        const uint2* Bs = (const uint2*)(sm + BOFF + (c & 1)*BBUF);
        if (wcol == 0) compute_chunk<7,0>(abase, Bs, acc, warpM, lane);
        else           compute_chunk<6,7>(abase, Bs, acc, warpM, lane);
        if (c < 63) sts(sm + ((c + 1) & 1)*ABUF);
        cp_wait0();
        __syncthreads();
    }

    int NT = wcol ? 6 : 7, ntbase = wcol ? 7 : 0;
    #pragma unroll
    for (int mt = 0; mt < 2; mt++){
        for (int nt = 0; nt < NT; nt++){
            int col = (ntbase + nt)*8 + 2*(lane & 3);
            if (col < 100){
                int r = (int)row0 + warpM + mt*16 + (lane >> 2);
                float b0 = sbc[col], b1 = sbc[col + 1];
                g_H[r*100 + col]           = fmaxf(acc[mt][nt][0] + b0, 0.f);
                g_H[r*100 + col + 1]       = fmaxf(acc[mt][nt][1] + b1, 0.f);
                g_H[(r + 8)*100 + col]     = fmaxf(acc[mt][nt][2] + b0, 0.f);
                g_H[(r + 8)*100 + col + 1] = fmaxf(acc[mt][nt][3] + b1, 0.f);
            }
        }
    }
}

// ---------------- 5: head layer 1 (packed f32x2; 512 x 128, single sample/thread) ----------------
__global__ void __launch_bounds__(128) k_head1(){
    __shared__ __align__(16) float sW1[100*52];
    __shared__ __align__(8) float sb1[52];
    int tid = threadIdx.x;
    int slot = blockIdx.x*128 + tid;
    int row = g_order[slot];
    int myhead = g_hidx[row];
    for (int hd = 0; hd < 8; hd++){
        if (!__syncthreads_or(myhead == hd)) continue;
        for (int i = tid; i < 5200; i += 128){
            int d = i / 52, j = i % 52;
            sW1[i] = (j < 50) ? g_W1f[hd*5000 + d*50 + j] : 0.f;
        }
        if (tid < 52) sb1[tid] = (tid < 50) ? g_b1f[hd*50 + tid] : 0.f;
        __syncthreads();
        if (myhead == hd){
            u64 o1p[26];
            #pragma unroll
            for (int jj = 0; jj < 26; jj++) o1p[jj] = *(const u64*)&sb1[2*jj];
            const float4* hp = (const float4*)(g_H + (size_t)row*100);
            for (int dv = 0; dv < 25; dv++){
                float4 hv = hp[dv];
                float hs[4] = {hv.x, hv.y, hv.z, hv.w};
                #pragma unroll
                for (int s = 0; s < 4; s++){
                    int d = dv*4 + s;
                    u64 vv = pack2(hs[s], hs[s]);
                    const ulonglong2* w2 = (const ulonglong2*)(sW1 + d*52);
                    #pragma unroll
                    for (int jj = 0; jj < 13; jj++){
                        ulonglong2 w = w2[jj];
                        fma2(o1p[2*jj],     vv, w.x);
                        fma2(o1p[2*jj + 1], vv, w.y);
                    }
                }
            }
            #pragma unroll
            for (int jj = 0; jj < 25; jj++){
                float2 o = unpack2(o1p[jj]);
                g_O1[(2*jj)*65536 + slot]     = fmaxf(o.x, 0.f);
                g_O1[(2*jj + 1)*65536 + slot] = fmaxf(o.y, 0.f);
            }
        }
        __syncthreads();
    }
}

// ---------------- 6: head layer 2 (packed f32x2) ----------------
// dyn smem: so1[128*52] @0, sW2[8 x 812] @26624, sb2[128] @52608
__global__ void __launch_bounds__(256) k_head2(float* __restrict__ out){
    extern __shared__ char hsm[];
    float* so1 = (float*)hsm;
    float* sW2 = (float*)(hsm + 26624);
    float* sb2 = (float*)(hsm + 52608);
    int tid = threadIdx.x;
    int slot0 = blockIdx.x*128;
    for (int i = tid; i < 6400; i += 256){
        int j = i >> 7, s = i & 127;
        so1[s*52 + j] = g_O1[j*65536 + slot0 + s];
    }
    int q = tid & 7;
    int sg = tid >> 3;
    int rows[4]; int hh[4];
    #pragma unroll
    for (int s = 0; s < 4; s++){
        rows[s] = g_order[slot0 + sg*4 + s];
        hh[s] = g_hidx[rows[s]];
    }
    for (int hd = 0; hd < 8; hd++){
        bool any = (hh[0]==hd)||(hh[1]==hd)||(hh[2]==hd)||(hh[3]==hd);
        if (!__syncthreads_or(any)) continue;
        for (int i = tid; i < 6400; i += 256){
            int j = i >> 7, d = i & 127, qq = d >> 4, cc = d & 15;
            sW2[qq*812 + j*16 + cc] = g_W2f[hd*6400 + i];
        }
        if (tid < 128) sb2[tid] = g_b2f[hd*128 + tid];
        __syncthreads();
        if (any){
            u64 accp[4][8];
            #pragma unroll
            for (int s = 0; s < 4; s++)
                #pragma unroll
                for (int u = 0; u < 8; u++)
                    accp[s][u] = *(const u64*)&sb2[q*16 + 2*u];
            const ulonglong2* wq = (const ulonglong2*)(sW2 + q*812);
            for (int j = 0; j < 50; j++){
                ulonglong2 w[4];
                #pragma unroll
                for (int u = 0; u < 4; u++) w[u] = wq[j*4 + u];
                #pragma unroll
                for (int s = 0; s < 4; s++){
                    float v = so1[(sg*4 + s)*52 + j];
                    u64 vv = pack2(v, v);
                    #pragma unroll
                    for (int u = 0; u < 4; u++){
                        fma2(accp[s][2*u],     vv, w[u].x);
                        fma2(accp[s][2*u + 1], vv, w[u].y);
                    }
                }
            }
            #pragma unroll
            for (int s = 0; s < 4; s++){
                if (hh[s] == hd){
                    float4* op = (float4*)(out + (size_t)rows[s]*128 + q*16);
                    #pragma unroll
                    for (int u = 0; u < 4; u++){
                        float2 a = unpack2(accp[s][2*u]);
                        float2 b = unpack2(accp[s][2*u + 1]);
                        op[u] = make_float4(a.x, a.y, b.x, b.y);
                    }
                }
            }
        }
        __syncthreads();
    }
}

// ---------------- launch (k_gemm at slot #4 for ncu) ----------------
extern "C" void kernel_launch(void* const* d_in, const int* in_sizes, int n_in,
                              void* d_out, int out_size){
    (void)in_sizes; (void)n_in; (void)out_size;
    const float* x  = (const float*)d_in[0];
    const float* m0 = (const float*)d_in[1];
    const float* v0 = (const float*)d_in[2];
    const float* Wn = (const float*)d_in[3];
    const float* bn = (const float*)d_in[4];
    const float* m1 = (const float*)d_in[5];
    const float* v1 = (const float*)d_in[6];
    const float* W1 = (const float*)d_in[7];
    const float* b1 = (const float*)d_in[8];
    const float* m2 = (const float*)d_in[9];
    const float* v2 = (const float*)d_in[10];
    const float* W2 = (const float*)d_in[11];
    const float* b2 = (const float*)d_in[12];
    float* out = (float*)d_out;

    cudaFuncSetAttribute(k_gemm,  cudaFuncAttributeMaxDynamicSharedMemorySize, 33792);
    cudaFuncSetAttribute(k_head2, cudaFuncAttributeMaxDynamicSharedMemorySize, 53120);

    k_prep<<<879, 256>>>(Wn, v0, m0, bn, m1, v1, W1, b1, m2, v2, W2, b2); // 1
    k_classify<<<256, 256>>>(x);                           // 2
    k_scatter<<<256, 256>>>();                             // 3
    k_gemm<<<512, 256, 33792>>>(x);                        // 4  <- ncu profiles launch #4
    k_head1<<<512, 128>>>();                               // 5
    k_head2<<<512, 256, 53120>>>(out);                     // 6
}

// round 17
// speedup vs baseline: 1.3756x; 1.0286x over previous
#include <cuda_runtime.h>
#include <cuda_fp16.h>
#include <cuda_bf16.h>

typedef unsigned int u32;
typedef unsigned long long u64;

#define EPS_BN 1e-5f

// ---------------- static device scratch ----------------
__device__ __align__(16) float g_H[65536*100];     // relu(gemm) [row][100]
__device__ __align__(16) float g_O1[50*65536];     // head L1 out, [j][slot]
__device__ __align__(16) u32   g_Bf[64*1664];      // B fp16 fragments
__device__ float g_bc[104];
__device__ __align__(16) float g_W1f[8*100*50];
__device__ float g_b1f[8*50];
__device__ __align__(16) float g_W2f[8*50*128];
__device__ float g_b2f[8*128];
__device__ int g_blkcnt[256*8];
__device__ unsigned char g_hidx[65536];
__device__ int g_order[65536];

// ---------------- helpers ----------------
__device__ __forceinline__ u32 smem_u32(const void* p){
    u32 a; asm("{ .reg .u64 t; cvta.to.shared.u64 t, %1; cvt.u32.u64 %0, t; }" : "=r"(a) : "l"(p)); return a;
}
__device__ __forceinline__ void cp_async16(u32 dst, const void* src){
    u64 g = (u64)__cvta_generic_to_global(src);
    asm volatile("cp.async.cg.shared.global [%0], [%1], 16;" :: "r"(dst), "l"(g) : "memory");
}
__device__ __forceinline__ void cp_commit(){ asm volatile("cp.async.commit_group;" ::: "memory"); }
__device__ __forceinline__ void cp_wait0(){ asm volatile("cp.async.wait_group 0;" ::: "memory"); }
__device__ __forceinline__ void ldm4(u32* d, u32 addr){
    asm volatile("ldmatrix.sync.aligned.m8n8.x4.shared.b16 {%0,%1,%2,%3}, [%4];"
        : "=r"(d[0]), "=r"(d[1]), "=r"(d[2]), "=r"(d[3]) : "r"(addr));
}
__device__ __forceinline__ void mma_f16(float* c, const u32* a, u32 b0, u32 b1){
    asm volatile("mma.sync.aligned.m16n8k16.row.col.f32.f16.f16.f32 "
        "{%0,%1,%2,%3}, {%4,%5,%6,%7}, {%8,%9}, {%0,%1,%2,%3};"
        : "+f"(c[0]), "+f"(c[1]), "+f"(c[2]), "+f"(c[3])
        : "r"(a[0]), "r"(a[1]), "r"(a[2]), "r"(a[3]), "r"(b0), "r"(b1));
}
__device__ __forceinline__ u32 packh2(float x, float y){
    __half2 h = __floats2half2_rn(x, y);
    return *(u32*)&h;
}
// packed fp32x2 helpers
__device__ __forceinline__ u64 pack2(float x, float y){
    u64 r; asm("mov.b64 %0, {%1, %2};" : "=l"(r) : "f"(x), "f"(y)); return r;
}
__device__ __forceinline__ float2 unpack2(u64 a){
    float2 r; asm("mov.b64 {%0, %1}, %2;" : "=f"(r.x), "=f"(r.y) : "l"(a)); return r;
}
__device__ __forceinline__ void fma2(u64& acc, u64 ab, u64 w){
    asm("fma.rn.f32x2 %0, %1, %2, %0;" : "+l"(acc) : "l"(ab), "l"(w));
}

// ---------------- prepGemm: B frags + bc fold (feeds gemm) ----------------
__global__ void k_prepGemm(const float* __restrict__ Wn, const float* __restrict__ v0,
                           const float* __restrict__ m0, const float* __restrict__ bn){
    int blk = blockIdx.x, tid = threadIdx.x;
    if (blk < 416){
        int i = blk*256 + tid;                 // 106496 B fragments
        int c = i / 1664;
        int rr = i % 1664;
        int reg = rr & 1;
        int t = rr >> 1;
        int lane = t & 31;
        int t2 = t >> 5;
        int nt = t2 % 13;
        int ks = t2 / 13;
        int k0 = c*32 + ks*16 + reg*8 + 2*(lane & 3);
        int n  = nt*8 + (lane >> 2);
        float a = 0.f, b = 0.f;
        if (n < 100){
            a = Wn[k0*100 + n]     * rsqrtf(__ldg(v0 + k0)   + EPS_BN);
            b = Wn[(k0+1)*100 + n] * rsqrtf(__ldg(v0 + k0+1) + EPS_BN);
        }
        g_Bf[i] = packh2(a, b);
        return;
    }
    __shared__ float red[256];
    int n = blk - 416;                         // 100 blocks for bc
    float s = 0.f;
    for (int k = tid; k < 2048; k += 256)
        s += m0[k] * rsqrtf(v0[k] + EPS_BN) * Wn[k*100 + n];
    red[tid] = s; __syncthreads();
    for (int st = 128; st; st >>= 1){ if (tid < st) red[tid] += red[tid + st]; __syncthreads(); }
    if (tid == 0) g_bc[n] = bn[n] - red[0];
}

// ---------------- prepHeads: W1f/b1f/W2f/b2f folds (feeds heads; overlaps gemm) -----
__global__ void k_prepHeads(const float* __restrict__ m1, const float* __restrict__ v1,
                            const float* __restrict__ W1, const float* __restrict__ b1,
                            const float* __restrict__ m2, const float* __restrict__ v2,
                            const float* __restrict__ W2, const float* __restrict__ b2){
    int blk = blockIdx.x, tid = threadIdx.x;
    if (blk < 157){
        int i = blk*256 + tid;
        if (i < 40000){ int d = (i / 50) % 100; g_W1f[i] = W1[i] * rsqrtf(v1[d] + EPS_BN); }
    } else if (blk < 159){
        int i = (blk - 157)*256 + tid;
        if (i < 400){
            int h = i / 50, j = i % 50;
            float s = 0.f;
            for (int d = 0; d < 100; d++)
                s += m1[d] * rsqrtf(v1[d] + EPS_BN) * W1[(h*100 + d)*50 + j];
            g_b1f[i] = b1[i] - s;
        }
    } else if (blk < 359){
        int i = (blk - 159)*256 + tid;
        if (i < 51200){ int hj = i >> 7; g_W2f[i] = W2[i] * rsqrtf(v2[hj] + EPS_BN); }
    } else {
        int i = (blk - 359)*256 + tid;
        if (i < 1024){
            int h = i >> 7, d = i & 127;
            float s = 0.f;
            for (int j = 0; j < 50; j++){
                int hj = h*50 + j;
                s += m2[hj] * rsqrtf(v2[hj] + EPS_BN) * W2[hj*128 + d];
            }
            g_b2f[i] = b2[i] - s;
        }
    }
}

// ---------------- classify (per-block histogram) ----------------
__global__ void k_classify(const float* __restrict__ x){
    __shared__ int c8[8];
    int tid = threadIdx.x;
    if (tid < 8) c8[tid] = 0;
    __syncthreads();
    int r = blockIdx.x*256 + tid;
    const float* xr = x + (size_t)r*2051;
    int idx = ((__ldg(xr)>0.5f)?4:0) | ((__ldg(xr+1)>0.5f)?2:0) | ((__ldg(xr+2)>0.5f)?1:0);
    g_hidx[r] = (unsigned char)idx;
    atomicAdd(&c8[idx], 1);
    __syncthreads();
    if (tid < 8) g_blkcnt[blockIdx.x*8 + tid] = c8[tid];
}

// ---------------- scatter with built-in scan ----------------
__global__ void k_scatter(){
    __shared__ int ssum[256];
    __shared__ int base8[8];
    __shared__ int c8[8];
    int t = threadIdx.x, blk = blockIdx.x;
    int v[8]; int s = 0;
    #pragma unroll
    for (int u = 0; u < 8; u++){
        int idx = t*8 + u;                     // idx = h*256 + b (head-major)
        v[u] = g_blkcnt[(idx & 255)*8 + (idx >> 8)];
        s += v[u];
    }
    ssum[t] = s; __syncthreads();
    for (int st = 1; st < 256; st <<= 1){
        int a = (t >= st) ? ssum[t - st] : 0;
        __syncthreads();
        ssum[t] += a;
        __syncthreads();
    }
    int base = t ? ssum[t-1] : 0;
    if (t < 8) c8[t] = 0;
    #pragma unroll
    for (int u = 0; u < 8; u++){
        int idx = t*8 + u;
        if ((idx & 255) == blk) base8[idx >> 8] = base;
        base += v[u];
    }
    __syncthreads();
    int r = blk*256 + t;
    int idx = g_hidx[r];
    int rank = atomicAdd(&c8[idx], 1);
    g_order[base8[idx] + rank] = r;
}

// ---------------- main GEMM: EXACT R7 shape (locked: ~152us) ----------------
// smem: A0[10240] A1[10240] B0[6656] B1[6656] = 33792 B
static constexpr int ABUF = 10240;
static constexpr int BOFF = 20480;
static constexpr int BBUF = 6656;

template<int NT, int NTBASE>
__device__ __forceinline__ void compute_chunk(u32 abase, const uint2* __restrict__ Bs,
                                              float (&acc)[2][7][4], int warpM, int lane){
    int rbase = warpM + (lane & 7) + ((lane >> 3) & 1)*8;
    int kcol  = (lane >> 4)*8;
    #pragma unroll
    for (int ks = 0; ks < 2; ks++){
        uint2 b[NT];
        #pragma unroll
        for (int nt = 0; nt < NT; nt++)
            b[nt] = Bs[(ks*13 + NTBASE + nt)*32 + lane];
        u32 ah[2][4];
        #pragma unroll
        for (int mt = 0; mt < 2; mt++){
            u32 ad = abase + (u32)(((rbase + mt*16)*40 + ks*16 + kcol)*2);
            ldm4(ah[mt], ad);
        }
        #pragma unroll
        for (int nt = 0; nt < NT; nt++)
            #pragma unroll
            for (int mt = 0; mt < 2; mt++)
                mma_f16(acc[mt][nt], ah[mt], b[nt].x, b[nt].y);
    }
}

__global__ void __launch_bounds__(256, 2) k_gemm(const float* __restrict__ x){
    extern __shared__ char sm[];
    __shared__ float sbc[104];
    int tid = threadIdx.x, lane = tid & 31, wid = tid >> 5;
    int warpM = (wid & 3) * 32;
    int wcol = wid >> 2;                       // 0: nt 0-6, 1: nt 7-12
    if (tid < 104) sbc[tid] = (tid < 100) ? g_bc[tid] : 0.f;
    u32 sa = smem_u32(sm);

    const size_t row0 = (size_t)blockIdx.x * 128;
    float acc[2][7][4];
    #pragma unroll
    for (int a = 0; a < 2; a++)
        #pragma unroll
        for (int b = 0; b < 7; b++)
            #pragma unroll
            for (int c = 0; c < 4; c++) acc[a][b][c] = 0.f;

    float2 pre[8];
    auto lda = [&](int c){
        #pragma unroll
        for (int j = 0; j < 8; j++){
            int e = tid + j*256;
            int r = e >> 4, kp = e & 15;
            const float* p = x + (row0 + r)*2051 + 3 + c*32 + kp*2;
            pre[j].x = __ldg(p); pre[j].y = __ldg(p + 1);
        }
    };
    auto sts = [&](char* buf){
        #pragma unroll
        for (int j = 0; j < 8; j++){
            int e = tid + j*256;
            int r = e >> 4, kp = e & 15;
            int off = (r*40 + kp*2)*2;
            *(u32*)(buf + off) = packh2(pre[j].x, pre[j].y);
        }
    };
    auto cpB = [&](int c, int buf){
        u32 dst = sa + BOFF + (u32)(buf*BBUF);
        const char* src = (const char*)g_Bf + (size_t)c*BBUF;
        #pragma unroll
        for (int i = 0; i < 2; i++){
            int e = tid + i*256;
            if (e < 416) cp_async16(dst + e*16, src + e*16);
        }
    };

    cpB(0, 0); cp_commit();
    lda(0); sts(sm);
    cp_wait0();
    __syncthreads();

    for (int c = 0; c < 64; c++){
        if (c < 63){ cpB(c + 1, (c + 1) & 1); cp_commit(); lda(c + 1); }
        u32 abase = sa + (u32)((c & 1)*ABUF);
        const uint2* Bs = (const uint2*)(sm + BOFF + (c & 1)*BBUF);
        if (wcol == 0) compute_chunk<7,0>(abase, Bs, acc, warpM, lane);
        else           compute_chunk<6,7>(abase, Bs, acc, warpM, lane);
        if (c < 63) sts(sm + ((c + 1) & 1)*ABUF);
        cp_wait0();
        __syncthreads();
    }

    int NT = wcol ? 6 : 7, ntbase = wcol ? 7 : 0;
    #pragma unroll
    for (int mt = 0; mt < 2; mt++){
        for (int nt = 0; nt < NT; nt++){
            int col = (ntbase + nt)*8 + 2*(lane & 3);
            if (col < 100){
                int r = (int)row0 + warpM + mt*16 + (lane >> 2);
                float b0 = sbc[col], b1 = sbc[col + 1];
                g_H[r*100 + col]           = fmaxf(acc[mt][nt][0] + b0, 0.f);
                g_H[r*100 + col + 1]       = fmaxf(acc[mt][nt][1] + b1, 0.f);
                g_H[(r + 8)*100 + col]     = fmaxf(acc[mt][nt][2] + b0, 0.f);
                g_H[(r + 8)*100 + col + 1] = fmaxf(acc[mt][nt][3] + b1, 0.f);
            }
        }
    }
}

// ---------------- head layer 1 (packed f32x2; head-range loop) ----------------
__global__ void __launch_bounds__(128) k_head1(){
    __shared__ __align__(16) float sW1[100*52];
    __shared__ __align__(8) float sb1[52];
    int tid = threadIdx.x;
    int slot0 = blockIdx.x*128;
    int slot = slot0 + tid;
    int row = g_order[slot];
    int myhead = g_hidx[row];
    int hFirst = g_hidx[g_order[slot0]];
    int hLast  = g_hidx[g_order[slot0 + 127]];
    for (int hd = hFirst; hd <= hLast; hd++){
        for (int i = tid; i < 5200; i += 128){
            int d = i / 52, j = i % 52;
            sW1[i] = (j < 50) ? g_W1f[hd*5000 + d*50 + j] : 0.f;
        }
        if (tid < 52) sb1[tid] = (tid < 50) ? g_b1f[hd*50 + tid] : 0.f;
        __syncthreads();
        if (myhead == hd){
            u64 o1p[26];
            #pragma unroll
            for (int jj = 0; jj < 26; jj++) o1p[jj] = *(const u64*)&sb1[2*jj];
            const float4* hp = (const float4*)(g_H + (size_t)row*100);
            for (int dv = 0; dv < 25; dv++){
                float4 hv = hp[dv];
                float hs[4] = {hv.x, hv.y, hv.z, hv.w};
                #pragma unroll
                for (int s = 0; s < 4; s++){
                    int d = dv*4 + s;
                    u64 vv = pack2(hs[s], hs[s]);
                    const ulonglong2* w2 = (const ulonglong2*)(sW1 + d*52);
                    #pragma unroll
                    for (int jj = 0; jj < 13; jj++){
                        ulonglong2 w = w2[jj];
                        fma2(o1p[2*jj],     vv, w.x);
                        fma2(o1p[2*jj + 1], vv, w.y);
                    }
                }
            }
            #pragma unroll
            for (int jj = 0; jj < 25; jj++){
                float2 o = unpack2(o1p[jj]);
                g_O1[(2*jj)*65536 + slot]     = fmaxf(o.x, 0.f);
                g_O1[(2*jj + 1)*65536 + slot] = fmaxf(o.y, 0.f);
            }
        }
        __syncthreads();
    }
}

// ---------------- head layer 2 (packed f32x2; head-range loop) ----------------
// dyn smem: so1[128*52] @0, sW2[8 x 812] @26624, sb2[128] @52608
__global__ void __launch_bounds__(256) k_head2(float* __restrict__ out){
    extern __shared__ char hsm[];
    float* so1 = (float*)hsm;
    float* sW2 = (float*)(hsm + 26624);
    float* sb2 = (float*)(hsm + 52608);
    int tid = threadIdx.x;
    int slot0 = blockIdx.x*128;
    for (int i = tid; i < 6400; i += 256){
        int j = i >> 7, s = i & 127;
        so1[s*52 + j] = g_O1[j*65536 + slot0 + s];
    }
    int q = tid & 7;
    int sg = tid >> 3;
    int rows[4]; int hh[4];
    #pragma unroll
    for (int s = 0; s < 4; s++){
        rows[s] = g_order[slot0 + sg*4 + s];
        hh[s] = g_hidx[rows[s]];
    }
    int hFirst = g_hidx[g_order[slot0]];
    int hLast  = g_hidx[g_order[slot0 + 127]];
    for (int hd = hFirst; hd <= hLast; hd++){
        bool any = (hh[0]==hd)||(hh[1]==hd)||(hh[2]==hd)||(hh[3]==hd);
        for (int i = tid; i < 6400; i += 256){
            int j = i >> 7, d = i & 127, qq = d >> 4, cc = d & 15;
            sW2[qq*812 + j*16 + cc] = g_W2f[hd*6400 + i];
        }
        if (tid < 128) sb2[tid] = g_b2f[hd*128 + tid];
        __syncthreads();
        if (any){
            u64 accp[4][8];
            #pragma unroll
            for (int s = 0; s < 4; s++)
                #pragma unroll
                for (int u = 0; u < 8; u++)
                    accp[s][u] = *(const u64*)&sb2[q*16 + 2*u];
            const ulonglong2* wq = (const ulonglong2*)(sW2 + q*812);
            for (int j = 0; j < 50; j++){
                ulonglong2 w[4];
                #pragma unroll
                for (int u = 0; u < 4; u++) w[u] = wq[j*4 + u];
                #pragma unroll
                for (int s = 0; s < 4; s++){
                    float v = so1[(sg*4 + s)*52 + j];
                    u64 vv = pack2(v, v);
                    #pragma unroll
                    for (int u = 0; u < 4; u++){
                        fma2(accp[s][2*u],     vv, w[u].x);
                        fma2(accp[s][2*u + 1], vv, w[u].y);
                    }
                }
            }
            #pragma unroll
            for (int s = 0; s < 4; s++){
                if (hh[s] == hd){
                    float4* op = (float4*)(out + (size_t)rows[s]*128 + q*16);
                    #pragma unroll
                    for (int u = 0; u < 4; u++){
                        float2 a = unpack2(accp[s][2*u]);
                        float2 b = unpack2(accp[s][2*u + 1]);
                        op[u] = make_float4(a.x, a.y, b.x, b.y);
                    }
                }
            }
        }
        __syncthreads();
    }
}

// ---------------- launch: fork/join graph ----------------
extern "C" void kernel_launch(void* const* d_in, const int* in_sizes, int n_in,
                              void* d_out, int out_size){
    (void)in_sizes; (void)n_in; (void)out_size;
    const float* x  = (const float*)d_in[0];
    const float* m0 = (const float*)d_in[1];
    const float* v0 = (const float*)d_in[2];
    const float* Wn = (const float*)d_in[3];
    const float* bn = (const float*)d_in[4];
    const float* m1 = (const float*)d_in[5];
    const float* v1 = (const float*)d_in[6];
    const float* W1 = (const float*)d_in[7];
    const float* b1 = (const float*)d_in[8];
    const float* m2 = (const float*)d_in[9];
    const float* v2 = (const float*)d_in[10];
    const float* W2 = (const float*)d_in[11];
    const float* b2 = (const float*)d_in[12];
    float* out = (float*)d_out;

    static cudaStream_t s2 = nullptr;
    static cudaEvent_t eFork = nullptr, eJoin = nullptr;
    if (s2 == nullptr){
        cudaStreamCreateWithFlags(&s2, cudaStreamNonBlocking);
        cudaEventCreateWithFlags(&eFork, cudaEventDisableTiming);
        cudaEventCreateWithFlags(&eJoin, cudaEventDisableTiming);
    }

    cudaFuncSetAttribute(k_gemm,  cudaFuncAttributeMaxDynamicSharedMemorySize, 33792);
    cudaFuncSetAttribute(k_head2, cudaFuncAttributeMaxDynamicSharedMemorySize, 53120);

    // fork: branch B (classify -> prepHeads -> scatter) runs concurrent with prepGemm+gemm
    cudaEventRecord(eFork, 0);
    cudaStreamWaitEvent(s2, eFork, 0);
    k_classify<<<256, 256, 0, s2>>>(x);
    k_prepHeads<<<363, 256, 0, s2>>>(m1, v1, W1, b1, m2, v2, W2, b2);
    k_scatter<<<256, 256, 0, s2>>>();
    cudaEventRecord(eJoin, s2);

    // branch A (main stream)
    k_prepGemm<<<516, 256>>>(Wn, v0, m0, bn);
    k_gemm<<<512, 256, 33792>>>(x);

    // join, then heads
    cudaStreamWaitEvent(0, eJoin, 0);
    k_head1<<<512, 128>>>();
    k_head2<<<512, 256, 53120>>>(out);
}